// round 2
// baseline (speedup 1.0000x reference)
#include <cuda_runtime.h>

#define D  512
#define TT 128
#define NN 64
#define SS 128

// ---- scratch (static device globals; no allocation) ----
__device__ float g_P[8192 * 512];        // pointer_embedding (T*N, D)
__device__ float g_qproj[384 * 512];     // src_e[0:6] @ W_obj[1024:1536]
__device__ float g_embproj[6 * 512];     // emb @ W_obj[512:1024]
__device__ float g_embdir[6 * 5];        // emb @ W_dir[512:1024]
__device__ float g_qdir[384 * 5];        // src_e[0:6] @ W_dir[1024:1536]
__device__ float g_rdir[384 * 5];        // src_e[0:6] @ W_dir[1536:2048]

// ---- packed f32x2 helpers (sm_103a FFMA2 path) ----
__device__ __forceinline__ unsigned long long bcast2(float x) {
    unsigned long long v;
    asm("mov.b64 %0, {%1, %1};" : "=l"(v) : "f"(x));
    return v;
}
__device__ __forceinline__ void ffma2(unsigned long long& d,
                                      unsigned long long a,
                                      unsigned long long b) {
    asm("fma.rn.f32x2 %0, %1, %2, %0;" : "+l"(d) : "l"(a), "l"(b));
}
__device__ __forceinline__ float2 unpack2(unsigned long long v) {
    float2 r;
    asm("mov.b64 {%0, %1}, %2;" : "=f"(r.x), "=f"(r.y) : "l"(v));
    return r;
}

// ============================================================
// emb projections: emb(6,512) @ W_obj[512:1024] and W_dir[512:1024]
// grid(6), block(512)
// ============================================================
__global__ void embproj_k(const float* __restrict__ emb,
                          const float* __restrict__ Wobj,
                          const float* __restrict__ Wdir) {
    __shared__ float e[D];
    int i = blockIdx.x;
    int tid = threadIdx.x;
    e[tid] = emb[i * D + tid];
    __syncthreads();
    float acc = 0.f;
    const float* wb = Wobj + (size_t)D * D + tid;
    #pragma unroll 8
    for (int k = 0; k < D; k++) acc += e[k] * wb[(size_t)k * D];
    g_embproj[i * D + tid] = acc;
    if (tid < 5) {
        float a = 0.f;
        const float* wd = Wdir + (size_t)D * 5 + tid;
        for (int k = 0; k < D; k++) a += e[k] * wd[k * 5];
        g_embdir[i * 5 + tid] = a;
    }
}

// ============================================================
// per-(i,n) src_e row dotted with W_dir[1024:1536] and [1536:2048]
// grid(384), block(128)
// ============================================================
__global__ __launch_bounds__(128) void srcdir_k(const float* __restrict__ srcE,
                                                const float* __restrict__ Wdir) {
    int r = blockIdx.x;
    int tid = threadIdx.x;
    float acc[10];
    #pragma unroll
    for (int j = 0; j < 10; j++) acc[j] = 0.f;
    const float* row = srcE + (size_t)r * D;
    for (int k = tid; k < D; k += 128) {
        float v = row[k];
        const float* w2 = Wdir + (size_t)(2 * D + k) * 5;
        const float* w3 = Wdir + (size_t)(3 * D + k) * 5;
        #pragma unroll
        for (int j = 0; j < 5; j++) {
            acc[j]     += v * w2[j];
            acc[5 + j] += v * w3[j];
        }
    }
    #pragma unroll
    for (int off = 16; off; off >>= 1)
        #pragma unroll
        for (int j = 0; j < 10; j++)
            acc[j] += __shfl_down_sync(0xffffffffu, acc[j], off);
    __shared__ float red[4][10];
    int w = tid >> 5, lane = tid & 31;
    if (lane == 0)
        #pragma unroll
        for (int j = 0; j < 10; j++) red[w][j] = acc[j];
    __syncthreads();
    if (tid < 10) {
        float s = red[0][tid] + red[1][tid] + red[2][tid] + red[3][tid];
        if (tid < 5) g_qdir[r * 5 + tid] = s;
        else         g_rdir[r * 5 + (tid - 5)] = s;
    }
}

// ============================================================
// Tiled SGEMM: C[M,512] = A[M,512] @ B[512,512] (row-major, ldb=512)
// 128x128 tile, K-tile 16, 256 threads, 8x8 per thread, FFMA2 packed,
// double-buffered smem.
// mode 0: C = g_qproj ; mode 1: C = g_P with gathered-bias epilogue
// ============================================================
__global__ __launch_bounds__(256, 2) void sgemm_k(const float* __restrict__ A,
                                                  const float* __restrict__ B,
                                                  int mode,
                                                  const int* __restrict__ tgt,
                                                  const float* __restrict__ b_obj) {
    __shared__ __align__(16) float As[2][16][132];
    __shared__ __align__(16) float Bs[2][16][132];
    const int tid = threadIdx.x;
    const int bm = blockIdx.x * 128;
    const int bn = blockIdx.y * 128;
    const int tx = tid & 15, ty = tid >> 4;

    const int a_row = tid >> 1;
    const int a_kk  = (tid & 1) * 8;
    const int b_kk  = tid >> 4;
    const int b_col = (tid & 15) * 8;

    const float* aBase = A + (size_t)(bm + a_row) * D + a_kk;
    const float* bBase = B + (size_t)b_kk * D + bn + b_col;

    // prologue: tile 0 -> buffer 0
    {
        float4 av0 = *(const float4*)(aBase);
        float4 av1 = *(const float4*)(aBase + 4);
        float4 bv0 = *(const float4*)(bBase);
        float4 bv1 = *(const float4*)(bBase + 4);
        As[0][a_kk + 0][a_row] = av0.x; As[0][a_kk + 1][a_row] = av0.y;
        As[0][a_kk + 2][a_row] = av0.z; As[0][a_kk + 3][a_row] = av0.w;
        As[0][a_kk + 4][a_row] = av1.x; As[0][a_kk + 5][a_row] = av1.y;
        As[0][a_kk + 6][a_row] = av1.z; As[0][a_kk + 7][a_row] = av1.w;
        *(float4*)&Bs[0][b_kk][b_col]     = bv0;
        *(float4*)&Bs[0][b_kk][b_col + 4] = bv1;
    }
    __syncthreads();

    unsigned long long acc[8][4];
    #pragma unroll
    for (int i = 0; i < 8; i++)
        #pragma unroll
        for (int j = 0; j < 4; j++) acc[i][j] = 0ull;

    const int NT = D / 16;
    float ar[8], br[8];

    for (int kt = 0; kt < NT; kt++) {
        if (kt + 1 < NT) {
            const float* ag = aBase + (kt + 1) * 16;
            const float* bg = bBase + (size_t)(kt + 1) * 16 * D;
            float4 t0 = *(const float4*)ag;
            float4 t1 = *(const float4*)(ag + 4);
            float4 t2 = *(const float4*)bg;
            float4 t3 = *(const float4*)(bg + 4);
            ar[0] = t0.x; ar[1] = t0.y; ar[2] = t0.z; ar[3] = t0.w;
            ar[4] = t1.x; ar[5] = t1.y; ar[6] = t1.z; ar[7] = t1.w;
            br[0] = t2.x; br[1] = t2.y; br[2] = t2.z; br[3] = t2.w;
            br[4] = t3.x; br[5] = t3.y; br[6] = t3.z; br[7] = t3.w;
        }
        const int cb = kt & 1;
        #pragma unroll
        for (int kk = 0; kk < 16; kk++) {
            float4 a0 = *(const float4*)&As[cb][kk][ty * 8];
            float4 a1 = *(const float4*)&As[cb][kk][ty * 8 + 4];
            const ulonglong2* bp = (const ulonglong2*)&Bs[cb][kk][tx * 8];
            ulonglong2 b01 = bp[0];
            ulonglong2 b23 = bp[1];
            float ra[8] = {a0.x, a0.y, a0.z, a0.w, a1.x, a1.y, a1.z, a1.w};
            #pragma unroll
            for (int i = 0; i < 8; i++) {
                unsigned long long ap = bcast2(ra[i]);
                ffma2(acc[i][0], ap, b01.x);
                ffma2(acc[i][1], ap, b01.y);
                ffma2(acc[i][2], ap, b23.x);
                ffma2(acc[i][3], ap, b23.y);
            }
        }
        if (kt + 1 < NT) {
            const int nb = (kt + 1) & 1;
            As[nb][a_kk + 0][a_row] = ar[0]; As[nb][a_kk + 1][a_row] = ar[1];
            As[nb][a_kk + 2][a_row] = ar[2]; As[nb][a_kk + 3][a_row] = ar[3];
            As[nb][a_kk + 4][a_row] = ar[4]; As[nb][a_kk + 5][a_row] = ar[5];
            As[nb][a_kk + 6][a_row] = ar[6]; As[nb][a_kk + 7][a_row] = ar[7];
            *(float4*)&Bs[nb][b_kk][b_col]     = make_float4(br[0], br[1], br[2], br[3]);
            *(float4*)&Bs[nb][b_kk][b_col + 4] = make_float4(br[4], br[5], br[6], br[7]);
            __syncthreads();
        }
    }

    if (mode == 0) {
        #pragma unroll
        for (int i = 0; i < 8; i++) {
            int r = bm + ty * 8 + i;
            float* cp = g_qproj + (size_t)r * D + bn + tx * 8;
            #pragma unroll
            for (int j = 0; j < 4; j++) {
                float2 v = unpack2(acc[i][j]);
                cp[2 * j] = v.x; cp[2 * j + 1] = v.y;
            }
        }
    } else {
        #pragma unroll
        for (int i = 0; i < 8; i++) {
            int r = bm + ty * 8 + i;
            int t = r >> 6, n = r & 63;
            int tp = (t + 1) & (TT - 1);
            const int* tg = tgt + ((size_t)tp * NN + n) * 3;
            int i0 = tg[0], i1 = tg[1];
            const float* ep = g_embproj + (size_t)i0 * D;
            const float* qp = g_qproj + ((size_t)i1 * NN + n) * D;
            float* cp = g_P + (size_t)r * D;
            #pragma unroll
            for (int j = 0; j < 4; j++) {
                float2 v = unpack2(acc[i][j]);
                int c0 = bn + tx * 8 + 2 * j;
                cp[c0]     = v.x + b_obj[c0]     + ep[c0]     + qp[c0];
                cp[c0 + 1] = v.y + b_obj[c0 + 1] + ep[c0 + 1] + qp[c0 + 1];
            }
        }
    }
}

// ============================================================
// einsum('snd,tnd->tns'): per n, C(128T x 128S) = P_n @ E_n^T, K=512
// grid(64, 2): n, T-half. 64x128 tile, 256 threads, 4x8 per thread,
// FFMA2 packed, double-buffered. Applies padding mask.
// ============================================================
__global__ __launch_bounds__(256, 2) void einsum_k(const float* __restrict__ srcE,
                                                   const unsigned char* __restrict__ mask,
                                                   float* __restrict__ out_obj) {
    __shared__ __align__(16) float As[2][16][68];
    __shared__ __align__(16) float Bs[2][16][132];
    const int n  = blockIdx.x;
    const int t0 = blockIdx.y * 64;
    const int tid = threadIdx.x;
    const int tx = tid & 15, ty = tid >> 4;

    const int a_row = tid >> 2;
    const int a_kk  = (tid & 3) * 4;
    const int b_row = tid >> 1;
    const int b_kk  = (tid & 1) * 8;

    const float* aBase = g_P + ((size_t)(t0 + a_row) * NN + n) * D + a_kk;
    const float* bBase = srcE + ((size_t)b_row * NN + n) * D + b_kk;

    {
        float4 av  = *(const float4*)(aBase);
        float4 bv0 = *(const float4*)(bBase);
        float4 bv1 = *(const float4*)(bBase + 4);
        As[0][a_kk + 0][a_row] = av.x; As[0][a_kk + 1][a_row] = av.y;
        As[0][a_kk + 2][a_row] = av.z; As[0][a_kk + 3][a_row] = av.w;
        Bs[0][b_kk + 0][b_row] = bv0.x; Bs[0][b_kk + 1][b_row] = bv0.y;
        Bs[0][b_kk + 2][b_row] = bv0.z; Bs[0][b_kk + 3][b_row] = bv0.w;
        Bs[0][b_kk + 4][b_row] = bv1.x; Bs[0][b_kk + 5][b_row] = bv1.y;
        Bs[0][b_kk + 6][b_row] = bv1.z; Bs[0][b_kk + 7][b_row] = bv1.w;
    }
    __syncthreads();

    unsigned long long acc[4][4];
    #pragma unroll
    for (int i = 0; i < 4; i++)
        #pragma unroll
        for (int j = 0; j < 4; j++) acc[i][j] = 0ull;

    const int NT = D / 16;
    float ar[4], br[8];

    for (int kt = 0; kt < NT; kt++) {
        if (kt + 1 < NT) {
            const float* ag = aBase + (kt + 1) * 16;
            const float* bg = bBase + (kt + 1) * 16;
            float4 t0v = *(const float4*)ag;
            float4 t2 = *(const float4*)bg;
            float4 t3 = *(const float4*)(bg + 4);
            ar[0] = t0v.x; ar[1] = t0v.y; ar[2] = t0v.z; ar[3] = t0v.w;
            br[0] = t2.x; br[1] = t2.y; br[2] = t2.z; br[3] = t2.w;
            br[4] = t3.x; br[5] = t3.y; br[6] = t3.z; br[7] = t3.w;
        }
        const int cb = kt & 1;
        #pragma unroll
        for (int kk = 0; kk < 16; kk++) {
            float4 a0 = *(const float4*)&As[cb][kk][ty * 4];
            const ulonglong2* bp = (const ulonglong2*)&Bs[cb][kk][tx * 8];
            ulonglong2 b01 = bp[0];
            ulonglong2 b23 = bp[1];
            float ra[4] = {a0.x, a0.y, a0.z, a0.w};
            #pragma unroll
            for (int i = 0; i < 4; i++) {
                unsigned long long ap = bcast2(ra[i]);
                ffma2(acc[i][0], ap, b01.x);
                ffma2(acc[i][1], ap, b01.y);
                ffma2(acc[i][2], ap, b23.x);
                ffma2(acc[i][3], ap, b23.y);
            }
        }
        if (kt + 1 < NT) {
            const int nb = (kt + 1) & 1;
            As[nb][a_kk + 0][a_row] = ar[0]; As[nb][a_kk + 1][a_row] = ar[1];
            As[nb][a_kk + 2][a_row] = ar[2]; As[nb][a_kk + 3][a_row] = ar[3];
            Bs[nb][b_kk + 0][b_row] = br[0]; Bs[nb][b_kk + 1][b_row] = br[1];
            Bs[nb][b_kk + 2][b_row] = br[2]; Bs[nb][b_kk + 3][b_row] = br[3];
            Bs[nb][b_kk + 4][b_row] = br[4]; Bs[nb][b_kk + 5][b_row] = br[5];
            Bs[nb][b_kk + 6][b_row] = br[6]; Bs[nb][b_kk + 7][b_row] = br[7];
            __syncthreads();
        }
    }

    const float NEG_INF = -__int_as_float(0x7f800000);
    #pragma unroll
    for (int i = 0; i < 4; i++) {
        int tt = t0 + ty * 4 + i;
        float* op = out_obj + ((size_t)tt * NN + n) * SS;
        #pragma unroll
        for (int j = 0; j < 4; j++) {
            float2 v = unpack2(acc[i][j]);
            int s0 = tx * 8 + 2 * j;
            op[s0]     = mask[n * SS + s0]     ? NEG_INF : v.x;
            op[s0 + 1] = mask[n * SS + s0 + 1] ? NEG_INF : v.y;
        }
    }
}

// ============================================================
// type_selections (6) + direction_selections (5).
// grid(128), block(256): each block handles 64 (t,n) rows,
// weights cached once in smem ([k*11+c], 11 coprime 32 -> conflict-free).
// ============================================================
__global__ __launch_bounds__(256) void typedir_k(const float* __restrict__ dec,
                                                 const int* __restrict__ tgt,
                                                 const float* __restrict__ Wt,
                                                 const float* __restrict__ bt,
                                                 const float* __restrict__ Wd,
                                                 const float* __restrict__ bd,
                                                 float* __restrict__ out_type,
                                                 float* __restrict__ out_dir) {
    __shared__ float sW[D * 11];
    const int tid = threadIdx.x;
    for (int i = tid; i < D * 6; i += 256) {
        int k = i / 6, c = i % 6;
        sW[k * 11 + c] = Wt[i];
    }
    for (int i = tid; i < D * 5; i += 256) {
        int k = i / 5, c = i % 5;
        sW[k * 11 + 6 + c] = Wd[i];
    }
    __syncthreads();

    const int w = tid >> 5, lane = tid & 31;
    const int r0 = blockIdx.x * 64;

    for (int rr = w; rr < 64; rr += 8) {
        int r = r0 + rr;
        const float* drow = dec + (size_t)r * D;
        float acc[11];
        #pragma unroll
        for (int c = 0; c < 11; c++) acc[c] = 0.f;
        #pragma unroll 4
        for (int u = 0; u < 16; u++) {
            int k = u * 32 + lane;
            float v = drow[k];
            const float* wp = &sW[k * 11];
            #pragma unroll
            for (int c = 0; c < 11; c++) acc[c] += v * wp[c];
        }
        #pragma unroll
        for (int off = 16; off; off >>= 1)
            #pragma unroll
            for (int c = 0; c < 11; c++)
                acc[c] += __shfl_xor_sync(0xffffffffu, acc[c], off);
        // all lanes hold full sums; lanes 0..10 write
        if (lane < 11) {
            int t = r >> 6, n = r & 63;
            int tp = (t + 1) & (TT - 1);
            const int* tg = tgt + ((size_t)tp * NN + n) * 3;
            if (lane < 6) {
                out_type[(size_t)r * 6 + lane] = acc[lane] + bt[lane];
            } else {
                int j = lane - 6;
                out_dir[(size_t)r * 5 + j] = acc[lane] + bd[j]
                    + g_embdir[tg[0] * 5 + j]
                    + g_qdir[((size_t)tg[1] * NN + n) * 5 + j]
                    + g_rdir[((size_t)tg[2] * NN + n) * 5 + j];
            }
        }
    }
}

// ============================================================
extern "C" void kernel_launch(void* const* d_in, const int* in_sizes, int n_in,
                              void* d_out, int out_size) {
    const float*         dec  = (const float*)d_in[0];   // (T,N,D)
    const int*           tgt  = (const int*)d_in[1];     // (T,N,3)
    const float*         srcE = (const float*)d_in[2];   // (S,N,D)
    const unsigned char* mask = (const unsigned char*)d_in[3]; // (N,S) bool
    const float*         emb  = (const float*)d_in[4];   // (6,D)
    const float*         Wt   = (const float*)d_in[5];   // (D,6)
    const float*         bt   = (const float*)d_in[6];   // (6,)
    const float*         Wo   = (const float*)d_in[7];   // (3D,D)
    const float*         bo   = (const float*)d_in[8];   // (D,)
    const float*         Wd   = (const float*)d_in[9];   // (4D,5)
    const float*         bd   = (const float*)d_in[10];  // (5,)

    float* out       = (float*)d_out;
    float* out_type  = out;                                   // (T,N,6)
    float* out_obj   = out + (size_t)TT * NN * 6;             // (T,N,S)
    float* out_dir   = out + (size_t)TT * NN * 6 + (size_t)TT * NN * SS; // (T,N,5)

    embproj_k<<<6, 512>>>(emb, Wo, Wd);
    srcdir_k<<<384, 128>>>(srcE, Wd);
    sgemm_k<<<dim3(3, 4), 256>>>(srcE, Wo + (size_t)2 * D * D, 0, tgt, bo);
    sgemm_k<<<dim3(64, 4), 256>>>(dec, Wo, 1, tgt, bo);
    einsum_k<<<dim3(64, 2), 256>>>(srcE, mask, out_obj);
    typedir_k<<<128, 256>>>(dec, tgt, Wt, bt, Wd, bd, out_type, out_dir);
}

// round 3
// speedup vs baseline: 1.4762x; 1.4762x over previous
#include <cuda_runtime.h>

#define D  512
#define TT 128
#define NN 64
#define SS 128

// ---- scratch (static device globals; no allocation) ----
__device__ float g_P[8192 * 512];        // pointer_embedding (T*N, D)
__device__ float g_qproj[384 * 512];     // src_e[0:6] @ W_obj[1024:1536]
__device__ float g_embproj[6 * 512];     // emb @ W_obj[512:1024]
__device__ float g_embdir[6 * 5];        // emb @ W_dir[512:1024]
__device__ float g_qdir[384 * 5];        // src_e[0:6] @ W_dir[1024:1536]
__device__ float g_rdir[384 * 5];        // src_e[0:6] @ W_dir[1536:2048]

// ============================================================
// emb projections: emb(6,512) @ W_obj[512:1024] and W_dir[512:1024]
// grid(6), block(512)
// ============================================================
__global__ void embproj_k(const float* __restrict__ emb,
                          const float* __restrict__ Wobj,
                          const float* __restrict__ Wdir) {
    __shared__ float e[D];
    int i = blockIdx.x;
    int tid = threadIdx.x;
    e[tid] = emb[i * D + tid];
    __syncthreads();
    float acc = 0.f;
    const float* wb = Wobj + (size_t)D * D + tid;
    #pragma unroll 8
    for (int k = 0; k < D; k++) acc += e[k] * wb[(size_t)k * D];
    g_embproj[i * D + tid] = acc;
    if (tid < 5) {
        float a = 0.f;
        const float* wd = Wdir + (size_t)D * 5 + tid;
        for (int k = 0; k < D; k++) a += e[k] * wd[k * 5];
        g_embdir[i * 5 + tid] = a;
    }
}

// ============================================================
// per-(i,n) src_e row dotted with W_dir[1024:1536] and [1536:2048]
// grid(384), block(128)
// ============================================================
__global__ __launch_bounds__(128) void srcdir_k(const float* __restrict__ srcE,
                                                const float* __restrict__ Wdir) {
    int r = blockIdx.x;
    int tid = threadIdx.x;
    float acc[10];
    #pragma unroll
    for (int j = 0; j < 10; j++) acc[j] = 0.f;
    const float* row = srcE + (size_t)r * D;
    for (int k = tid; k < D; k += 128) {
        float v = row[k];
        const float* w2 = Wdir + (size_t)(2 * D + k) * 5;
        const float* w3 = Wdir + (size_t)(3 * D + k) * 5;
        #pragma unroll
        for (int j = 0; j < 5; j++) {
            acc[j]     += v * w2[j];
            acc[5 + j] += v * w3[j];
        }
    }
    #pragma unroll
    for (int off = 16; off; off >>= 1)
        #pragma unroll
        for (int j = 0; j < 10; j++)
            acc[j] += __shfl_down_sync(0xffffffffu, acc[j], off);
    __shared__ float red[4][10];
    int w = tid >> 5, lane = tid & 31;
    if (lane == 0)
        #pragma unroll
        for (int j = 0; j < 10; j++) red[w][j] = acc[j];
    __syncthreads();
    if (tid < 10) {
        float s = red[0][tid] + red[1][tid] + red[2][tid] + red[3][tid];
        if (tid < 5) g_qdir[r * 5 + tid] = s;
        else         g_rdir[r * 5 + (tid - 5)] = s;
    }
}

// ============================================================
// Tiled SGEMM: C[M,512] = A[M,512] @ B[512,512]   (B row-major, ldb=512)
// 128x128 tile, K-tile 16, 256 threads, 8x8 per thread.  (R1 form)
// mode 0: C = g_qproj (plain)
// mode 1: C = g_P, epilogue adds b_obj + gathered emb_proj + gathered q_proj
// ============================================================
__global__ __launch_bounds__(256) void sgemm_k(const float* __restrict__ A,
                                               const float* __restrict__ B,
                                               int mode,
                                               const int* __restrict__ tgt,
                                               const float* __restrict__ b_obj) {
    __shared__ __align__(16) float As[16][132];
    __shared__ __align__(16) float Bs[16][132];
    const int tid = threadIdx.x;
    const int bm = blockIdx.x * 128;
    const int bn = blockIdx.y * 128;
    const int tx = tid & 15, ty = tid >> 4;

    const int a_row = tid >> 1;
    const int a_kk  = (tid & 1) * 8;
    const int b_kk  = tid >> 4;
    const int b_col = (tid & 15) * 8;

    float acc[8][8];
    #pragma unroll
    for (int i = 0; i < 8; i++)
        #pragma unroll
        for (int j = 0; j < 8; j++) acc[i][j] = 0.f;

    const float* aBase = A + (size_t)(bm + a_row) * D + a_kk;
    const float* bBase = B + (size_t)b_kk * D + bn + b_col;

    for (int k0 = 0; k0 < D; k0 += 16) {
        float4 av0 = *(const float4*)(aBase + k0);
        float4 av1 = *(const float4*)(aBase + k0 + 4);
        float4 bv0 = *(const float4*)(bBase + (size_t)k0 * D);
        float4 bv1 = *(const float4*)(bBase + (size_t)k0 * D + 4);
        As[a_kk + 0][a_row] = av0.x; As[a_kk + 1][a_row] = av0.y;
        As[a_kk + 2][a_row] = av0.z; As[a_kk + 3][a_row] = av0.w;
        As[a_kk + 4][a_row] = av1.x; As[a_kk + 5][a_row] = av1.y;
        As[a_kk + 6][a_row] = av1.z; As[a_kk + 7][a_row] = av1.w;
        *(float4*)&Bs[b_kk][b_col]     = bv0;
        *(float4*)&Bs[b_kk][b_col + 4] = bv1;
        __syncthreads();
        #pragma unroll
        for (int kk = 0; kk < 16; kk++) {
            float ra[8], rb[8];
            #pragma unroll
            for (int i = 0; i < 8; i++) ra[i] = As[kk][ty * 8 + i];
            #pragma unroll
            for (int j = 0; j < 8; j++) rb[j] = Bs[kk][tx * 8 + j];
            #pragma unroll
            for (int i = 0; i < 8; i++)
                #pragma unroll
                for (int j = 0; j < 8; j++) acc[i][j] += ra[i] * rb[j];
        }
        __syncthreads();
    }

    if (mode == 0) {
        #pragma unroll
        for (int i = 0; i < 8; i++) {
            int r = bm + ty * 8 + i;
            float* cp = g_qproj + (size_t)r * D + bn + tx * 8;
            #pragma unroll
            for (int j = 0; j < 8; j++) cp[j] = acc[i][j];
        }
    } else {
        #pragma unroll
        for (int i = 0; i < 8; i++) {
            int r = bm + ty * 8 + i;
            int t = r >> 6, n = r & 63;
            int tp = (t + 1) & (TT - 1);
            const int* tg = tgt + ((size_t)tp * NN + n) * 3;
            int i0 = tg[0], i1 = tg[1];
            const float* ep = g_embproj + (size_t)i0 * D;
            const float* qp = g_qproj + ((size_t)i1 * NN + n) * D;
            float* cp = g_P + (size_t)r * D;
            #pragma unroll
            for (int j = 0; j < 8; j++) {
                int c = bn + tx * 8 + j;
                cp[c] = acc[i][j] + b_obj[c] + ep[c] + qp[c];
            }
        }
    }
}

// ============================================================
// einsum('snd,tnd->tns'): per n, C(128T x 128S) = P_n @ E_n^T, K=512
// grid(64, 2): n, T-half. 64x128 tile, 256 threads, 4x8 per thread. (R1 form)
// ============================================================
__global__ __launch_bounds__(256) void einsum_k(const float* __restrict__ srcE,
                                                const unsigned char* __restrict__ mask,
                                                float* __restrict__ out_obj) {
    __shared__ __align__(16) float As[16][68];    // [kk][t] t-tile 64
    __shared__ __align__(16) float Bs[16][132];   // [kk][s] s 128
    const int n  = blockIdx.x;
    const int t0 = blockIdx.y * 64;
    const int tid = threadIdx.x;
    const int tx = tid & 15, ty = tid >> 4;

    const int a_row = tid >> 2;
    const int a_kk  = (tid & 3) * 4;
    const int b_row = tid >> 1;
    const int b_kk  = (tid & 1) * 8;

    float acc[4][8];
    #pragma unroll
    for (int i = 0; i < 4; i++)
        #pragma unroll
        for (int j = 0; j < 8; j++) acc[i][j] = 0.f;

    const float* aBase = g_P + ((size_t)(t0 + a_row) * NN + n) * D + a_kk;
    const float* bBase = srcE + ((size_t)b_row * NN + n) * D + b_kk;

    for (int k0 = 0; k0 < D; k0 += 16) {
        float4 av  = *(const float4*)(aBase + k0);
        float4 bv0 = *(const float4*)(bBase + k0);
        float4 bv1 = *(const float4*)(bBase + k0 + 4);
        As[a_kk + 0][a_row] = av.x; As[a_kk + 1][a_row] = av.y;
        As[a_kk + 2][a_row] = av.z; As[a_kk + 3][a_row] = av.w;
        Bs[b_kk + 0][b_row] = bv0.x; Bs[b_kk + 1][b_row] = bv0.y;
        Bs[b_kk + 2][b_row] = bv0.z; Bs[b_kk + 3][b_row] = bv0.w;
        Bs[b_kk + 4][b_row] = bv1.x; Bs[b_kk + 5][b_row] = bv1.y;
        Bs[b_kk + 6][b_row] = bv1.z; Bs[b_kk + 7][b_row] = bv1.w;
        __syncthreads();
        #pragma unroll
        for (int kk = 0; kk < 16; kk++) {
            float ra[4], rb[8];
            #pragma unroll
            for (int i = 0; i < 4; i++) ra[i] = As[kk][ty * 4 + i];
            #pragma unroll
            for (int j = 0; j < 8; j++) rb[j] = Bs[kk][tx * 8 + j];
            #pragma unroll
            for (int i = 0; i < 4; i++)
                #pragma unroll
                for (int j = 0; j < 8; j++) acc[i][j] += ra[i] * rb[j];
        }
        __syncthreads();
    }

    #pragma unroll
    for (int i = 0; i < 4; i++) {
        int tt = t0 + ty * 4 + i;
        float* op = out_obj + ((size_t)tt * NN + n) * SS + tx * 8;
        #pragma unroll
        for (int j = 0; j < 8; j++) {
            int s = tx * 8 + j;
            op[j] = mask[n * SS + s] ? -__int_as_float(0x7f800000) : acc[i][j];
        }
    }
}

// ============================================================
// type_selections (6) + direction_selections (5).
// grid(128), block(256): each block handles 64 (t,n) rows,
// weights cached once in smem ([k*11+c], 11 coprime 32 -> conflict-free).
// ============================================================
__global__ __launch_bounds__(256) void typedir_k(const float* __restrict__ dec,
                                                 const int* __restrict__ tgt,
                                                 const float* __restrict__ Wt,
                                                 const float* __restrict__ bt,
                                                 const float* __restrict__ Wd,
                                                 const float* __restrict__ bd,
                                                 float* __restrict__ out_type,
                                                 float* __restrict__ out_dir) {
    __shared__ float sW[D * 11];
    const int tid = threadIdx.x;
    for (int i = tid; i < D * 6; i += 256) {
        int k = i / 6, c = i % 6;
        sW[k * 11 + c] = Wt[i];
    }
    for (int i = tid; i < D * 5; i += 256) {
        int k = i / 5, c = i % 5;
        sW[k * 11 + 6 + c] = Wd[i];
    }
    __syncthreads();

    const int w = tid >> 5, lane = tid & 31;
    const int r0 = blockIdx.x * 64;

    for (int rr = w; rr < 64; rr += 8) {
        int r = r0 + rr;
        const float* drow = dec + (size_t)r * D;
        float acc[11];
        #pragma unroll
        for (int c = 0; c < 11; c++) acc[c] = 0.f;
        #pragma unroll 4
        for (int u = 0; u < 16; u++) {
            int k = u * 32 + lane;
            float v = drow[k];
            const float* wp = &sW[k * 11];
            #pragma unroll
            for (int c = 0; c < 11; c++) acc[c] += v * wp[c];
        }
        #pragma unroll
        for (int off = 16; off; off >>= 1)
            #pragma unroll
            for (int c = 0; c < 11; c++)
                acc[c] += __shfl_xor_sync(0xffffffffu, acc[c], off);
        if (lane < 11) {
            int t = r >> 6, n = r & 63;
            int tp = (t + 1) & (TT - 1);
            const int* tg = tgt + ((size_t)tp * NN + n) * 3;
            if (lane < 6) {
                out_type[(size_t)r * 6 + lane] = acc[lane] + bt[lane];
            } else {
                int j = lane - 6;
                out_dir[(size_t)r * 5 + j] = acc[lane] + bd[j]
                    + g_embdir[tg[0] * 5 + j]
                    + g_qdir[((size_t)tg[1] * NN + n) * 5 + j]
                    + g_rdir[((size_t)tg[2] * NN + n) * 5 + j];
            }
        }
    }
}

// ============================================================
extern "C" void kernel_launch(void* const* d_in, const int* in_sizes, int n_in,
                              void* d_out, int out_size) {
    const float*         dec  = (const float*)d_in[0];   // (T,N,D)
    const int*           tgt  = (const int*)d_in[1];     // (T,N,3)
    const float*         srcE = (const float*)d_in[2];   // (S,N,D)
    const unsigned char* mask = (const unsigned char*)d_in[3]; // (N,S) bool
    const float*         emb  = (const float*)d_in[4];   // (6,D)
    const float*         Wt   = (const float*)d_in[5];   // (D,6)
    const float*         bt   = (const float*)d_in[6];   // (6,)
    const float*         Wo   = (const float*)d_in[7];   // (3D,D)
    const float*         bo   = (const float*)d_in[8];   // (D,)
    const float*         Wd   = (const float*)d_in[9];   // (4D,5)
    const float*         bd   = (const float*)d_in[10];  // (5,)

    float* out       = (float*)d_out;
    float* out_type  = out;                                   // (T,N,6)
    float* out_obj   = out + (size_t)TT * NN * 6;             // (T,N,S)
    float* out_dir   = out + (size_t)TT * NN * 6 + (size_t)TT * NN * SS; // (T,N,5)

    embproj_k<<<6, 512>>>(emb, Wo, Wd);
    srcdir_k<<<384, 128>>>(srcE, Wd);
    sgemm_k<<<dim3(3, 4), 256>>>(srcE, Wo + (size_t)2 * D * D, 0, tgt, bo);
    sgemm_k<<<dim3(64, 4), 256>>>(dec, Wo, 1, tgt, bo);
    einsum_k<<<dim3(64, 2), 256>>>(srcE, mask, out_obj);
    typedir_k<<<128, 256>>>(dec, tgt, Wt, bt, Wd, bd, out_type, out_dir);
}

// round 4
// speedup vs baseline: 2.2242x; 1.5067x over previous
#include <cuda_runtime.h>

#define D  512
#define TT 128
#define NN 64
#define SS 128

// ---- scratch (static device globals; no allocation) ----
__device__ float g_P[8192 * 512];        // dec @ W_obj[0:512] + b_obj
__device__ float g_qproj[384 * 512];     // src_e[0:6] @ W_obj[1024:1536]
__device__ float g_embproj[6 * 512];     // emb @ W_obj[512:1024]
__device__ float g_embdir[6 * 5];        // emb @ W_dir[512:1024]
__device__ float g_qdir[384 * 5];        // src_e[0:6] @ W_dir[1024:1536]
__device__ float g_rdir[384 * 5];        // src_e[0:6] @ W_dir[1536:2048]

// ============================================================
// GEMM tile worker: C[bm:bm+128, bn:bn+128] = A[.,512] @ B[512,512] (+bias)
// 256 threads, 8x8 per thread, K-tile 16. sm must hold 4224 floats.
// ============================================================
__device__ __forceinline__ void gemm_tile(const float* __restrict__ A,
                                          const float* __restrict__ B,
                                          float* __restrict__ C,
                                          const float* __restrict__ bias,
                                          int bm, int bn, float* sm) {
    float (*As)[132] = (float(*)[132])sm;
    float (*Bs)[132] = (float(*)[132])(sm + 16 * 132);
    const int tid = threadIdx.x;
    const int tx = tid & 15, ty = tid >> 4;

    const int a_row = tid >> 1;
    const int a_kk  = (tid & 1) * 8;
    const int b_kk  = tid >> 4;
    const int b_col = (tid & 15) * 8;

    float acc[8][8];
    #pragma unroll
    for (int i = 0; i < 8; i++)
        #pragma unroll
        for (int j = 0; j < 8; j++) acc[i][j] = 0.f;

    const float* aBase = A + (size_t)(bm + a_row) * D + a_kk;
    const float* bBase = B + (size_t)b_kk * D + bn + b_col;

    for (int k0 = 0; k0 < D; k0 += 16) {
        float4 av0 = *(const float4*)(aBase + k0);
        float4 av1 = *(const float4*)(aBase + k0 + 4);
        float4 bv0 = *(const float4*)(bBase + (size_t)k0 * D);
        float4 bv1 = *(const float4*)(bBase + (size_t)k0 * D + 4);
        As[a_kk + 0][a_row] = av0.x; As[a_kk + 1][a_row] = av0.y;
        As[a_kk + 2][a_row] = av0.z; As[a_kk + 3][a_row] = av0.w;
        As[a_kk + 4][a_row] = av1.x; As[a_kk + 5][a_row] = av1.y;
        As[a_kk + 6][a_row] = av1.z; As[a_kk + 7][a_row] = av1.w;
        *(float4*)&Bs[b_kk][b_col]     = bv0;
        *(float4*)&Bs[b_kk][b_col + 4] = bv1;
        __syncthreads();
        #pragma unroll
        for (int kk = 0; kk < 16; kk++) {
            float ra[8], rb[8];
            #pragma unroll
            for (int i = 0; i < 8; i++) ra[i] = As[kk][ty * 8 + i];
            #pragma unroll
            for (int j = 0; j < 8; j++) rb[j] = Bs[kk][tx * 8 + j];
            #pragma unroll
            for (int i = 0; i < 8; i++)
                #pragma unroll
                for (int j = 0; j < 8; j++) acc[i][j] += ra[i] * rb[j];
        }
        __syncthreads();
    }

    #pragma unroll
    for (int i = 0; i < 8; i++) {
        int r = bm + ty * 8 + i;
        float* cp = C + (size_t)r * D + bn + tx * 8;
        if (bias) {
            const float* bp = bias + bn + tx * 8;
            #pragma unroll
            for (int j = 0; j < 8; j++) cp[j] = acc[i][j] + bp[j];
        } else {
            #pragma unroll
            for (int j = 0; j < 8; j++) cp[j] = acc[i][j];
        }
    }
}

// ============================================================
// Stage 1 mega-kernel: 466 blocks x 256 threads
//   [0,256)   : g_P = dec @ W_obj[0:512] + b_obj
//   [256,268) : g_qproj = src_e[0:6] @ W_obj[1024:1536]
//   [268,274) : embproj (+ embdir)
//   [274,466) : srcdir (2 rows per block)
// ============================================================
__global__ __launch_bounds__(256) void stage1_k(const float* __restrict__ dec,
                                                const float* __restrict__ srcE,
                                                const float* __restrict__ emb,
                                                const float* __restrict__ Wo,
                                                const float* __restrict__ bo,
                                                const float* __restrict__ Wdir) {
    __shared__ __align__(16) float sm[4224];
    const int bid = blockIdx.x;
    const int tid = threadIdx.x;

    if (bid < 256) {
        gemm_tile(dec, Wo, g_P, bo, (bid >> 2) * 128, (bid & 3) * 128, sm);
    } else if (bid < 268) {
        int q = bid - 256;
        gemm_tile(srcE, Wo + (size_t)2 * D * D, g_qproj, (const float*)0,
                  (q >> 2) * 128, (q & 3) * 128, sm);
    } else if (bid < 274) {
        // embproj: emb(6,512) @ W_obj[512:1024]; also embdir
        int i = bid - 268;
        float* e = sm;
        e[tid]       = emb[i * D + tid];
        e[tid + 256] = emb[i * D + tid + 256];
        __syncthreads();
        #pragma unroll
        for (int half = 0; half < 2; half++) {
            int c = tid + half * 256;
            float acc = 0.f;
            const float* wb = Wo + (size_t)D * D + c;
            #pragma unroll 8
            for (int k = 0; k < D; k++) acc += e[k] * wb[(size_t)k * D];
            g_embproj[i * D + c] = acc;
        }
        if (tid < 5) {
            float a = 0.f;
            const float* wd = Wdir + (size_t)D * 5 + tid;
            for (int k = 0; k < D; k++) a += e[k] * wd[k * 5];
            g_embdir[i * 5 + tid] = a;
        }
    } else {
        // srcdir: rows 2*(bid-274) + group
        const int g  = tid >> 7;
        const int lt = tid & 127;
        const int r  = (bid - 274) * 2 + g;
        float acc[10];
        #pragma unroll
        for (int j = 0; j < 10; j++) acc[j] = 0.f;
        const float* row = srcE + (size_t)r * D;
        for (int k = lt; k < D; k += 128) {
            float v = row[k];
            const float* w2 = Wdir + (size_t)(2 * D + k) * 5;
            const float* w3 = Wdir + (size_t)(3 * D + k) * 5;
            #pragma unroll
            for (int j = 0; j < 5; j++) {
                acc[j]     += v * w2[j];
                acc[5 + j] += v * w3[j];
            }
        }
        #pragma unroll
        for (int off = 16; off; off >>= 1)
            #pragma unroll
            for (int j = 0; j < 10; j++)
                acc[j] += __shfl_down_sync(0xffffffffu, acc[j], off);
        float* red = sm;                        // 8 warps x 10
        const int w = tid >> 5, lane = tid & 31;
        if (lane == 0)
            #pragma unroll
            for (int j = 0; j < 10; j++) red[w * 10 + j] = acc[j];
        __syncthreads();
        if (lt < 10) {
            int wb = g * 4;
            float s = red[(wb + 0) * 10 + lt] + red[(wb + 1) * 10 + lt]
                    + red[(wb + 2) * 10 + lt] + red[(wb + 3) * 10 + lt];
            if (lt < 5) g_qdir[r * 5 + lt] = s;
            else        g_rdir[r * 5 + (lt - 5)] = s;
        }
    }
}

// ============================================================
// Stage 2 kernel: 256 blocks x 256 threads
//   [0,128)   : einsum with gathered A-load (P = g_P + embproj[tg0] + qproj[tg1])
//   [128,256) : typedir
// ============================================================
__global__ __launch_bounds__(256) void stage2_k(const float* __restrict__ srcE,
                                                const unsigned char* __restrict__ mask,
                                                const int* __restrict__ tgt,
                                                const float* __restrict__ dec,
                                                const float* __restrict__ Wt,
                                                const float* __restrict__ bt,
                                                const float* __restrict__ Wd,
                                                const float* __restrict__ bd,
                                                float* __restrict__ out_type,
                                                float* __restrict__ out_obj,
                                                float* __restrict__ out_dir) {
    __shared__ __align__(16) float sm[5632];
    const int bid = blockIdx.x;
    const int tid = threadIdx.x;

    if (bid < 128) {
        // einsum('snd,tnd->tns') for one n, 64 t-rows
        float (*As)[68]  = (float(*)[68])sm;               // 16 x 68
        float (*Bs)[132] = (float(*)[132])(sm + 16 * 68);  // 16 x 132
        const int n  = bid >> 1;
        const int t0 = (bid & 1) * 64;
        const int tx = tid & 15, ty = tid >> 4;

        const int a_row = tid >> 2;
        const int a_kk  = (tid & 3) * 4;
        const int b_row = tid >> 1;
        const int b_kk  = (tid & 1) * 8;

        // gathered A bases (row fixed per thread)
        const int t  = t0 + a_row;
        const int tp = (t + 1) & (TT - 1);
        const int* tg = tgt + ((size_t)tp * NN + n) * 3;
        const float* aBase  = g_P + ((size_t)t * NN + n) * D + a_kk;
        const float* epBase = g_embproj + (size_t)tg[0] * D + a_kk;
        const float* qpBase = g_qproj + ((size_t)tg[1] * NN + n) * D + a_kk;
        const float* bBase  = srcE + ((size_t)b_row * NN + n) * D + b_kk;

        float acc[4][8];
        #pragma unroll
        for (int i = 0; i < 4; i++)
            #pragma unroll
            for (int j = 0; j < 8; j++) acc[i][j] = 0.f;

        for (int k0 = 0; k0 < D; k0 += 16) {
            float4 av = *(const float4*)(aBase + k0);
            float4 ev = *(const float4*)(epBase + k0);
            float4 qv = *(const float4*)(qpBase + k0);
            av.x = (av.x + ev.x) + qv.x;
            av.y = (av.y + ev.y) + qv.y;
            av.z = (av.z + ev.z) + qv.z;
            av.w = (av.w + ev.w) + qv.w;
            float4 bv0 = *(const float4*)(bBase + k0);
            float4 bv1 = *(const float4*)(bBase + k0 + 4);
            As[a_kk + 0][a_row] = av.x; As[a_kk + 1][a_row] = av.y;
            As[a_kk + 2][a_row] = av.z; As[a_kk + 3][a_row] = av.w;
            Bs[b_kk + 0][b_row] = bv0.x; Bs[b_kk + 1][b_row] = bv0.y;
            Bs[b_kk + 2][b_row] = bv0.z; Bs[b_kk + 3][b_row] = bv0.w;
            Bs[b_kk + 4][b_row] = bv1.x; Bs[b_kk + 5][b_row] = bv1.y;
            Bs[b_kk + 6][b_row] = bv1.z; Bs[b_kk + 7][b_row] = bv1.w;
            __syncthreads();
            #pragma unroll
            for (int kk = 0; kk < 16; kk++) {
                float ra[4], rb[8];
                #pragma unroll
                for (int i = 0; i < 4; i++) ra[i] = As[kk][ty * 4 + i];
                #pragma unroll
                for (int j = 0; j < 8; j++) rb[j] = Bs[kk][tx * 8 + j];
                #pragma unroll
                for (int i = 0; i < 4; i++)
                    #pragma unroll
                    for (int j = 0; j < 8; j++) acc[i][j] += ra[i] * rb[j];
            }
            __syncthreads();
        }

        #pragma unroll
        for (int i = 0; i < 4; i++) {
            int tt = t0 + ty * 4 + i;
            float* op = out_obj + ((size_t)tt * NN + n) * SS + tx * 8;
            #pragma unroll
            for (int j = 0; j < 8; j++) {
                int s = tx * 8 + j;
                op[j] = mask[n * SS + s] ? -__int_as_float(0x7f800000) : acc[i][j];
            }
        }
    } else {
        // typedir: 64 rows per block, weights staged in smem (stride 11)
        float* sW = sm;                                    // 512 x 11
        for (int i = tid; i < D * 6; i += 256) {
            int k = i / 6, c = i % 6;
            sW[k * 11 + c] = Wt[i];
        }
        for (int i = tid; i < D * 5; i += 256) {
            int k = i / 5, c = i % 5;
            sW[k * 11 + 6 + c] = Wd[i];
        }
        __syncthreads();

        const int w = tid >> 5, lane = tid & 31;
        const int r0 = (bid - 128) * 64;

        for (int rr = w; rr < 64; rr += 8) {
            int r = r0 + rr;
            const float* drow = dec + (size_t)r * D;
            float acc[11];
            #pragma unroll
            for (int c = 0; c < 11; c++) acc[c] = 0.f;
            #pragma unroll 4
            for (int u = 0; u < 16; u++) {
                int k = u * 32 + lane;
                float v = drow[k];
                const float* wp = &sW[k * 11];
                #pragma unroll
                for (int c = 0; c < 11; c++) acc[c] += v * wp[c];
            }
            #pragma unroll
            for (int off = 16; off; off >>= 1)
                #pragma unroll
                for (int c = 0; c < 11; c++)
                    acc[c] += __shfl_xor_sync(0xffffffffu, acc[c], off);
            if (lane < 11) {
                int t = r >> 6, n = r & 63;
                int tp = (t + 1) & (TT - 1);
                const int* tg = tgt + ((size_t)tp * NN + n) * 3;
                if (lane < 6) {
                    out_type[(size_t)r * 6 + lane] = acc[lane] + bt[lane];
                } else {
                    int j = lane - 6;
                    out_dir[(size_t)r * 5 + j] = acc[lane] + bd[j]
                        + g_embdir[tg[0] * 5 + j]
                        + g_qdir[((size_t)tg[1] * NN + n) * 5 + j]
                        + g_rdir[((size_t)tg[2] * NN + n) * 5 + j];
                }
            }
        }
    }
}

// ============================================================
extern "C" void kernel_launch(void* const* d_in, const int* in_sizes, int n_in,
                              void* d_out, int out_size) {
    const float*         dec  = (const float*)d_in[0];   // (T,N,D)
    const int*           tgt  = (const int*)d_in[1];     // (T,N,3)
    const float*         srcE = (const float*)d_in[2];   // (S,N,D)
    const unsigned char* mask = (const unsigned char*)d_in[3]; // (N,S) bool
    const float*         emb  = (const float*)d_in[4];   // (6,D)
    const float*         Wt   = (const float*)d_in[5];   // (D,6)
    const float*         bt   = (const float*)d_in[6];   // (6,)
    const float*         Wo   = (const float*)d_in[7];   // (3D,D)
    const float*         bo   = (const float*)d_in[8];   // (D,)
    const float*         Wd   = (const float*)d_in[9];   // (4D,5)
    const float*         bd   = (const float*)d_in[10];  // (5,)

    float* out       = (float*)d_out;
    float* out_type  = out;                                   // (T,N,6)
    float* out_obj   = out + (size_t)TT * NN * 6;             // (T,N,S)
    float* out_dir   = out + (size_t)TT * NN * 6 + (size_t)TT * NN * SS; // (T,N,5)

    stage1_k<<<466, 256>>>(dec, srcE, emb, Wo, bo, Wd);
    stage2_k<<<256, 256>>>(srcE, mask, tgt, dec, Wt, bt, Wd, bd,
                           out_type, out_obj, out_dir);
}

// round 5
// speedup vs baseline: 2.2688x; 1.0200x over previous
#include <cuda_runtime.h>

#define D  512
#define TT 128
#define NN 64
#define SS 128

// ---- scratch (static device globals; no allocation) ----
__device__ float g_P[8192 * 512];        // dec @ W_obj[0:512] + b_obj
__device__ float g_qproj[384 * 512];     // src_e[0:6] @ W_obj[1024:1536]
__device__ float g_embproj[6 * 512];     // emb @ W_obj[512:1024]
__device__ float g_embdir[6 * 5];        // emb @ W_dir[512:1024]
__device__ float g_qdir[384 * 5];        // src_e[0:6] @ W_dir[1024:1536]
__device__ float g_rdir[384 * 5];        // src_e[0:6] @ W_dir[1536:2048]

// ============================================================
// GEMM tile worker: C[bm:bm+128, bn:bn+128] = A[.,512] @ B[512,512] (+bias)
// 256 threads, 8x8 per thread, K-tile 16. sm must hold 4224 floats.
// ============================================================
__device__ __forceinline__ void gemm_tile(const float* __restrict__ A,
                                          const float* __restrict__ B,
                                          float* __restrict__ C,
                                          const float* __restrict__ bias,
                                          int bm, int bn, float* sm) {
    float (*As)[132] = (float(*)[132])sm;
    float (*Bs)[132] = (float(*)[132])(sm + 16 * 132);
    const int tid = threadIdx.x;
    const int tx = tid & 15, ty = tid >> 4;

    const int a_row = tid >> 1;
    const int a_kk  = (tid & 1) * 8;
    const int b_kk  = tid >> 4;
    const int b_col = (tid & 15) * 8;

    float acc[8][8];
    #pragma unroll
    for (int i = 0; i < 8; i++)
        #pragma unroll
        for (int j = 0; j < 8; j++) acc[i][j] = 0.f;

    const float* aBase = A + (size_t)(bm + a_row) * D + a_kk;
    const float* bBase = B + (size_t)b_kk * D + bn + b_col;

    for (int k0 = 0; k0 < D; k0 += 16) {
        float4 av0 = *(const float4*)(aBase + k0);
        float4 av1 = *(const float4*)(aBase + k0 + 4);
        float4 bv0 = *(const float4*)(bBase + (size_t)k0 * D);
        float4 bv1 = *(const float4*)(bBase + (size_t)k0 * D + 4);
        As[a_kk + 0][a_row] = av0.x; As[a_kk + 1][a_row] = av0.y;
        As[a_kk + 2][a_row] = av0.z; As[a_kk + 3][a_row] = av0.w;
        As[a_kk + 4][a_row] = av1.x; As[a_kk + 5][a_row] = av1.y;
        As[a_kk + 6][a_row] = av1.z; As[a_kk + 7][a_row] = av1.w;
        *(float4*)&Bs[b_kk][b_col]     = bv0;
        *(float4*)&Bs[b_kk][b_col + 4] = bv1;
        __syncthreads();
        #pragma unroll
        for (int kk = 0; kk < 16; kk++) {
            float ra[8], rb[8];
            #pragma unroll
            for (int i = 0; i < 8; i++) ra[i] = As[kk][ty * 8 + i];
            #pragma unroll
            for (int j = 0; j < 8; j++) rb[j] = Bs[kk][tx * 8 + j];
            #pragma unroll
            for (int i = 0; i < 8; i++)
                #pragma unroll
                for (int j = 0; j < 8; j++) acc[i][j] += ra[i] * rb[j];
        }
        __syncthreads();
    }

    #pragma unroll
    for (int i = 0; i < 8; i++) {
        int r = bm + ty * 8 + i;
        float* cp = C + (size_t)r * D + bn + tx * 8;
        if (bias) {
            const float* bp = bias + bn + tx * 8;
            #pragma unroll
            for (int j = 0; j < 8; j++) cp[j] = acc[i][j] + bp[j];
        } else {
            #pragma unroll
            for (int j = 0; j < 8; j++) cp[j] = acc[i][j];
        }
    }
}

// ============================================================
// Stage 1 mega-kernel: 466 blocks x 256 threads
//   [0,256)   : g_P = dec @ W_obj[0:512] + b_obj
//   [256,268) : g_qproj = src_e[0:6] @ W_obj[1024:1536]
//   [268,274) : embproj (+ embdir)
//   [274,466) : srcdir (2 rows per block)
// ============================================================
__global__ __launch_bounds__(256) void stage1_k(const float* __restrict__ dec,
                                                const float* __restrict__ srcE,
                                                const float* __restrict__ emb,
                                                const float* __restrict__ Wo,
                                                const float* __restrict__ bo,
                                                const float* __restrict__ Wdir) {
    __shared__ __align__(16) float sm[4224];
    const int bid = blockIdx.x;
    const int tid = threadIdx.x;

    if (bid < 256) {
        gemm_tile(dec, Wo, g_P, bo, (bid >> 2) * 128, (bid & 3) * 128, sm);
    } else if (bid < 268) {
        int q = bid - 256;
        gemm_tile(srcE, Wo + (size_t)2 * D * D, g_qproj, (const float*)0,
                  (q >> 2) * 128, (q & 3) * 128, sm);
    } else if (bid < 274) {
        int i = bid - 268;
        float* e = sm;
        e[tid]       = emb[i * D + tid];
        e[tid + 256] = emb[i * D + tid + 256];
        __syncthreads();
        #pragma unroll
        for (int half = 0; half < 2; half++) {
            int c = tid + half * 256;
            float acc = 0.f;
            const float* wb = Wo + (size_t)D * D + c;
            #pragma unroll 8
            for (int k = 0; k < D; k++) acc += e[k] * wb[(size_t)k * D];
            g_embproj[i * D + c] = acc;
        }
        if (tid < 5) {
            float a = 0.f;
            const float* wd = Wdir + (size_t)D * 5 + tid;
            for (int k = 0; k < D; k++) a += e[k] * wd[k * 5];
            g_embdir[i * 5 + tid] = a;
        }
    } else {
        const int g  = tid >> 7;
        const int lt = tid & 127;
        const int r  = (bid - 274) * 2 + g;
        float acc[10];
        #pragma unroll
        for (int j = 0; j < 10; j++) acc[j] = 0.f;
        const float* row = srcE + (size_t)r * D;
        for (int k = lt; k < D; k += 128) {
            float v = row[k];
            const float* w2 = Wdir + (size_t)(2 * D + k) * 5;
            const float* w3 = Wdir + (size_t)(3 * D + k) * 5;
            #pragma unroll
            for (int j = 0; j < 5; j++) {
                acc[j]     += v * w2[j];
                acc[5 + j] += v * w3[j];
            }
        }
        #pragma unroll
        for (int off = 16; off; off >>= 1)
            #pragma unroll
            for (int j = 0; j < 10; j++)
                acc[j] += __shfl_down_sync(0xffffffffu, acc[j], off);
        float* red = sm;
        const int w = tid >> 5, lane = tid & 31;
        if (lane == 0)
            #pragma unroll
            for (int j = 0; j < 10; j++) red[w * 10 + j] = acc[j];
        __syncthreads();
        if (lt < 10) {
            int wb = g * 4;
            float s = red[(wb + 0) * 10 + lt] + red[(wb + 1) * 10 + lt]
                    + red[(wb + 2) * 10 + lt] + red[(wb + 3) * 10 + lt];
            if (lt < 5) g_qdir[r * 5 + lt] = s;
            else        g_rdir[r * 5 + (lt - 5)] = s;
        }
    }
}

// ============================================================
// Stage 2 kernel: 256 blocks x 256 threads
//   [0,128)   : einsum with gathered A-load, DOUBLE-BUFFERED + prefetch
//   [128,256) : typedir
// ============================================================
__global__ __launch_bounds__(256) void stage2_k(const float* __restrict__ srcE,
                                                const unsigned char* __restrict__ mask,
                                                const int* __restrict__ tgt,
                                                const float* __restrict__ dec,
                                                const float* __restrict__ Wt,
                                                const float* __restrict__ bt,
                                                const float* __restrict__ Wd,
                                                const float* __restrict__ bd,
                                                float* __restrict__ out_type,
                                                float* __restrict__ out_obj,
                                                float* __restrict__ out_dir) {
    __shared__ __align__(16) float sm[6400];
    const int bid = blockIdx.x;
    const int tid = threadIdx.x;

    if (bid < 128) {
        // einsum('snd,tnd->tns') for one n, 64 t-rows, double-buffered
        float (*As)[16][68]  = (float(*)[16][68])sm;                // 2 x 16 x 68
        float (*Bs)[16][132] = (float(*)[16][132])(sm + 2 * 16 * 68);
        const int n  = bid >> 1;
        const int t0 = (bid & 1) * 64;
        const int tx = tid & 15, ty = tid >> 4;

        const int a_row = tid >> 2;
        const int a_kk  = (tid & 3) * 4;
        const int b_row = tid >> 1;
        const int b_kk  = (tid & 1) * 8;

        const int t  = t0 + a_row;
        const int tp = (t + 1) & (TT - 1);
        const int* tg = tgt + ((size_t)tp * NN + n) * 3;
        const int i0 = tg[0], i1 = tg[1];
        const float* aBase  = g_P + ((size_t)t * NN + n) * D + a_kk;
        const float* epBase = g_embproj + (size_t)i0 * D + a_kk;
        const float* qpBase = g_qproj + ((size_t)i1 * NN + n) * D + a_kk;
        const float* bBase  = srcE + ((size_t)b_row * NN + n) * D + b_kk;

        float acc[4][8];
        #pragma unroll
        for (int i = 0; i < 4; i++)
            #pragma unroll
            for (int j = 0; j < 8; j++) acc[i][j] = 0.f;

        // prologue: tile 0 -> buffer 0
        {
            float4 av = *(const float4*)(aBase);
            float4 ev = *(const float4*)(epBase);
            float4 qv = *(const float4*)(qpBase);
            float4 bv0 = *(const float4*)(bBase);
            float4 bv1 = *(const float4*)(bBase + 4);
            As[0][a_kk + 0][a_row] = (av.x + ev.x) + qv.x;
            As[0][a_kk + 1][a_row] = (av.y + ev.y) + qv.y;
            As[0][a_kk + 2][a_row] = (av.z + ev.z) + qv.z;
            As[0][a_kk + 3][a_row] = (av.w + ev.w) + qv.w;
            Bs[0][b_kk + 0][b_row] = bv0.x; Bs[0][b_kk + 1][b_row] = bv0.y;
            Bs[0][b_kk + 2][b_row] = bv0.z; Bs[0][b_kk + 3][b_row] = bv0.w;
            Bs[0][b_kk + 4][b_row] = bv1.x; Bs[0][b_kk + 5][b_row] = bv1.y;
            Bs[0][b_kk + 6][b_row] = bv1.z; Bs[0][b_kk + 7][b_row] = bv1.w;
        }
        __syncthreads();

        const int NT = D / 16;   // 32
        for (int kt = 0; kt < NT; kt++) {
            float4 av, ev, qv, bv0, bv1;
            const bool more = (kt + 1 < NT);
            if (more) {
                int k0 = (kt + 1) * 16;
                av  = *(const float4*)(aBase + k0);
                ev  = *(const float4*)(epBase + k0);
                qv  = *(const float4*)(qpBase + k0);
                bv0 = *(const float4*)(bBase + k0);
                bv1 = *(const float4*)(bBase + k0 + 4);
            }
            const int cb = kt & 1;
            #pragma unroll
            for (int kk = 0; kk < 16; kk++) {
                float ra[4], rb[8];
                #pragma unroll
                for (int i = 0; i < 4; i++) ra[i] = As[cb][kk][ty * 4 + i];
                #pragma unroll
                for (int j = 0; j < 8; j++) rb[j] = Bs[cb][kk][tx * 8 + j];
                #pragma unroll
                for (int i = 0; i < 4; i++)
                    #pragma unroll
                    for (int j = 0; j < 8; j++) acc[i][j] += ra[i] * rb[j];
            }
            if (more) {
                const int nb = cb ^ 1;
                As[nb][a_kk + 0][a_row] = (av.x + ev.x) + qv.x;
                As[nb][a_kk + 1][a_row] = (av.y + ev.y) + qv.y;
                As[nb][a_kk + 2][a_row] = (av.z + ev.z) + qv.z;
                As[nb][a_kk + 3][a_row] = (av.w + ev.w) + qv.w;
                Bs[nb][b_kk + 0][b_row] = bv0.x; Bs[nb][b_kk + 1][b_row] = bv0.y;
                Bs[nb][b_kk + 2][b_row] = bv0.z; Bs[nb][b_kk + 3][b_row] = bv0.w;
                Bs[nb][b_kk + 4][b_row] = bv1.x; Bs[nb][b_kk + 5][b_row] = bv1.y;
                Bs[nb][b_kk + 6][b_row] = bv1.z; Bs[nb][b_kk + 7][b_row] = bv1.w;
                __syncthreads();
            }
        }

        #pragma unroll
        for (int i = 0; i < 4; i++) {
            int tt = t0 + ty * 4 + i;
            float* op = out_obj + ((size_t)tt * NN + n) * SS + tx * 8;
            #pragma unroll
            for (int j = 0; j < 8; j++) {
                int s = tx * 8 + j;
                op[j] = mask[n * SS + s] ? -__int_as_float(0x7f800000) : acc[i][j];
            }
        }
    } else {
        // typedir: 64 rows per block, weights staged in smem (stride 11)
        float* sW = sm;                                    // 512 x 11
        for (int i = tid; i < D * 6; i += 256) {
            int k = i / 6, c = i % 6;
            sW[k * 11 + c] = Wt[i];
        }
        for (int i = tid; i < D * 5; i += 256) {
            int k = i / 5, c = i % 5;
            sW[k * 11 + 6 + c] = Wd[i];
        }
        __syncthreads();

        const int w = tid >> 5, lane = tid & 31;
        const int r0 = (bid - 128) * 64;

        for (int rr = w; rr < 64; rr += 8) {
            int r = r0 + rr;
            const float* drow = dec + (size_t)r * D;
            float acc[11];
            #pragma unroll
            for (int c = 0; c < 11; c++) acc[c] = 0.f;
            #pragma unroll 4
            for (int u = 0; u < 16; u++) {
                int k = u * 32 + lane;
                float v = drow[k];
                const float* wp = &sW[k * 11];
                #pragma unroll
                for (int c = 0; c < 11; c++) acc[c] += v * wp[c];
            }
            #pragma unroll
            for (int off = 16; off; off >>= 1)
                #pragma unroll
                for (int c = 0; c < 11; c++)
                    acc[c] += __shfl_xor_sync(0xffffffffu, acc[c], off);
            if (lane < 11) {
                int t = r >> 6, n = r & 63;
                int tp = (t + 1) & (TT - 1);
                const int* tg = tgt + ((size_t)tp * NN + n) * 3;
                if (lane < 6) {
                    out_type[(size_t)r * 6 + lane] = acc[lane] + bt[lane];
                } else {
                    int j = lane - 6;
                    out_dir[(size_t)r * 5 + j] = acc[lane] + bd[j]
                        + g_embdir[tg[0] * 5 + j]
                        + g_qdir[((size_t)tg[1] * NN + n) * 5 + j]
                        + g_rdir[((size_t)tg[2] * NN + n) * 5 + j];
                }
            }
        }
    }
}

// ============================================================
extern "C" void kernel_launch(void* const* d_in, const int* in_sizes, int n_in,
                              void* d_out, int out_size) {
    const float*         dec  = (const float*)d_in[0];   // (T,N,D)
    const int*           tgt  = (const int*)d_in[1];     // (T,N,3)
    const float*         srcE = (const float*)d_in[2];   // (S,N,D)
    const unsigned char* mask = (const unsigned char*)d_in[3]; // (N,S) bool
    const float*         emb  = (const float*)d_in[4];   // (6,D)
    const float*         Wt   = (const float*)d_in[5];   // (D,6)
    const float*         bt   = (const float*)d_in[6];   // (6,)
    const float*         Wo   = (const float*)d_in[7];   // (3D,D)
    const float*         bo   = (const float*)d_in[8];   // (D,)
    const float*         Wd   = (const float*)d_in[9];   // (4D,5)
    const float*         bd   = (const float*)d_in[10];  // (5,)

    float* out       = (float*)d_out;
    float* out_type  = out;                                   // (T,N,6)
    float* out_obj   = out + (size_t)TT * NN * 6;             // (T,N,S)
    float* out_dir   = out + (size_t)TT * NN * 6 + (size_t)TT * NN * SS; // (T,N,5)

    stage1_k<<<466, 256>>>(dec, srcE, emb, Wo, bo, Wd);
    stage2_k<<<256, 256>>>(srcE, mask, tgt, dec, Wt, bt, Wd, bd,
                           out_type, out_obj, out_dir);
}